// round 9
// baseline (speedup 1.0000x reference)
#include <cuda_runtime.h>
#include <cuda_bf16.h>
#include <cstdint>

// DrugBAN fused kernel, R8: bulk-async (UBLKCP/TMA path) for target_h,
// R1 LDG shape for drug_x.
//
// Algebra (verified, rel_err ~2e-7): softmax rows sum to 1, so
//   drug_ctx[b,:] = (1/NT) * segment_sum(drug_x)  (rank < NMAX only)
//   tgt_ctx[b,:]  = mean_t target_h[b,t,:]
// W_a / GEMM / softmax cancel.
//
// R1..R7: every SM-side restructuring (occupancy/balance/width/contiguity)
// left BW pinned at ~5.6 TB/s with DRAM only ~50% -> the limiter is the
// per-thread LDG issue/L1tex path (5M LDG.128 ~= 34K cyc/SM ~= measured).
// R8 moves the 64MB target tensor through cp.async.bulk into SMEM (no LDG
// issue cost; TMA streams at the LTS cap) and reduces from SMEM via LDS.
//
// Inputs: d_in[0] drug_x f32[16384,256], d_in[1] batch_idx i32[16384] sorted,
//         d_in[2] target_h f32[64,1024,256], d_in[3] W_a (unused).
// Output: f32 [64, 512] = [drug_ctx | tgt_ctx].

#define NT_LEN     1024
#define NMAX_CAP   512
#define BATCH_B    64
#define TCH        8          // target chunks per batch (blocks)
#define ROWS_BLK   (NT_LEN / TCH)   // 128 rows per target block
#define CHUNK_ROWS 8
#define NCHUNK     (ROWS_BLK / CHUNK_ROWS)  // 16
#define CHUNK_BYTES (CHUNK_ROWS * 256 * 4)  // 8192
#define STAGES     4

__device__ float g_tpart[BATCH_B * TCH * 256];
__device__ int   g_ttk[BATCH_B];   // zero-init; self-resetting

// ---------------- mbarrier / bulk-async helpers ----------------
__device__ __forceinline__ uint32_t smem_u32(const void* p) {
    return (uint32_t)__cvta_generic_to_shared(p);
}
__device__ __forceinline__ void mbar_init(uint32_t a, uint32_t cnt) {
    asm volatile("mbarrier.init.shared.b64 [%0], %1;" :: "r"(a), "r"(cnt) : "memory");
}
__device__ __forceinline__ void mbar_expect_tx(uint32_t a, uint32_t bytes) {
    asm volatile("mbarrier.arrive.expect_tx.shared.b64 _, [%0], %1;"
                 :: "r"(a), "r"(bytes) : "memory");
}
__device__ __forceinline__ void mbar_wait(uint32_t a, uint32_t phase) {
    asm volatile(
        "{\n\t"
        ".reg .pred P;\n\t"
        "WAIT_%=:\n\t"
        "mbarrier.try_wait.parity.acquire.cta.shared::cta.b64 P, [%0], %1, 0x989680;\n\t"
        "@P bra.uni DONE_%=;\n\t"
        "bra.uni WAIT_%=;\n\t"
        "DONE_%=:\n\t"
        "}" :: "r"(a), "r"(phase) : "memory");
}
__device__ __forceinline__ void bulk_ld(uint32_t dst, const void* src,
                                        uint32_t bytes, uint32_t mbar) {
    asm volatile(
        "cp.async.bulk.shared::cluster.global.mbarrier::complete_tx::bytes "
        "[%0], [%1], %2, [%3];"
        :: "r"(dst), "l"(src), "r"(bytes), "r"(mbar) : "memory");
}

__device__ __forceinline__ int lb_search(const int* __restrict__ a, int n, int key) {
    int lo = 0, hi = n;
    while (lo < hi) {
        int mid = (lo + hi) >> 1;
        if (__ldg(a + mid) < key) lo = mid + 1; else hi = mid;
    }
    return lo;
}
__device__ __forceinline__ void f4_add(float4& d, const float4 s) {
    d.x += s.x; d.y += s.y; d.z += s.z; d.w += s.w;
}

__global__ __launch_bounds__(256)
void drugban_fused_kernel(const float* __restrict__ drug_x,
                          const int*   __restrict__ batch_idx,
                          const float* __restrict__ target_h,
                          float*       __restrict__ out,
                          int n_nodes) {
    const int b    = blockIdx.x;     // batch 0..63
    const int part = blockIdx.y;     // 0..3 drug quarters, 4..11 target chunks
    const int tid  = threadIdx.x;    // 256 threads

    __shared__ __align__(128) float4 s_tile[STAGES * CHUNK_ROWS * 64]; // 32 KB
    __shared__ __align__(8) uint64_t s_mbar[STAGES];
    __shared__ float4 red[256];      // 4 KB
    __shared__ int s_ticket;

    const float scale = 1.0f / (float)NT_LEN;

    if (part < 4) {
        // ================= drug: exact R1 shape (LDG) =================
        const int col = tid & 15;    // float4 column within the 64-dim slice
        const int rg  = tid >> 4;    // 0..15 row group

        int start = lb_search(batch_idx, n_nodes, b);
        int end   = lb_search(batch_idx, n_nodes, b + 1);
        if (end - start > NMAX_CAP) end = start + NMAX_CAP;

        const float4* base = reinterpret_cast<const float4*>(drug_x)
                             + (size_t)part * 16 + col;   // row = 64 float4
        float4 acc = make_float4(0.f, 0.f, 0.f, 0.f);
        int i = start + rg;
        for (; i + 16 < end; i += 32) {
            float4 v0 = __ldg(base + (size_t)i * 64);
            float4 v1 = __ldg(base + (size_t)(i + 16) * 64);
            acc.x += v0.x + v1.x; acc.y += v0.y + v1.y;
            acc.z += v0.z + v1.z; acc.w += v0.w + v1.w;
        }
        if (i < end) f4_add(acc, __ldg(base + (size_t)i * 64));

        red[tid] = acc;
        __syncthreads();
        #pragma unroll
        for (int s = 128; s >= 16; s >>= 1) {
            if (tid < s) f4_add(red[tid], red[tid + s]);
            __syncthreads();
        }
        if (tid < 16) {
            float4 r = red[tid];
            r.x *= scale; r.y *= scale; r.z *= scale; r.w *= scale;
            reinterpret_cast<float4*>(out + b * 512 + part * 64)[tid] = r;
        }
    } else {
        // ============ target: bulk-async pipeline + SMEM reduce ============
        const int c   = part - 4;            // 0..7
        const int col = tid & 63;            // float4 col within 256-dim row
        const int rgp = tid >> 6;            // 0..3 row group

        const char* src_base = reinterpret_cast<const char*>(
            target_h + (size_t)b * (NT_LEN * 256) + (size_t)c * ROWS_BLK * 256);

        uint32_t tile0 = smem_u32(s_tile);
        uint32_t mb0   = smem_u32(s_mbar);

        if (tid == 0) {
            #pragma unroll
            for (int s = 0; s < STAGES; s++) mbar_init(mb0 + s * 8, 1);
        }
        __syncthreads();
        asm volatile("fence.proxy.async.shared::cta;" ::: "memory");

        // prologue: fill the ring
        if (tid == 0) {
            #pragma unroll
            for (int s = 0; s < STAGES; s++) {
                mbar_expect_tx(mb0 + s * 8, CHUNK_BYTES);
                bulk_ld(tile0 + s * CHUNK_BYTES,
                        src_base + (size_t)s * CHUNK_BYTES,
                        CHUNK_BYTES, mb0 + s * 8);
            }
        }

        float4 acc = make_float4(0.f, 0.f, 0.f, 0.f);
        for (int i = 0; i < NCHUNK; i++) {
            const int s  = i & (STAGES - 1);
            const int ph = (i >> 2) & 1;
            mbar_wait(mb0 + s * 8, ph);

            const float4* tp = s_tile + s * (CHUNK_ROWS * 64);
            // 8 rows per chunk: this thread takes rows rgp and rgp+4
            f4_add(acc, tp[rgp * 64 + col]);
            f4_add(acc, tp[(rgp + 4) * 64 + col]);
            __syncthreads();   // all reads of slot s done

            if (tid == 0 && i + STAGES < NCHUNK) {
                mbar_expect_tx(mb0 + s * 8, CHUNK_BYTES);
                bulk_ld(tile0 + s * CHUNK_BYTES,
                        src_base + (size_t)(i + STAGES) * CHUNK_BYTES,
                        CHUNK_BYTES, mb0 + s * 8);
            }
        }

        // reduce 4 row groups (layout rgp*64 + col) -> 64 float4 partial
        red[tid] = acc;
        __syncthreads();
        if (tid < 128) f4_add(red[tid], red[tid + 128]);
        __syncthreads();
        if (tid < 64)  f4_add(red[tid], red[tid + 64]);
        __syncthreads();

        if (tid < 64)
            reinterpret_cast<float4*>(g_tpart + (b * TCH + c) * 256)[tid] = red[tid];

        __threadfence();
        __syncthreads();
        if (tid == 0) s_ticket = atomicAdd(&g_ttk[b], 1);
        __syncthreads();

        if (s_ticket == TCH - 1) {
            __threadfence();   // acquire peers' partials
            if (tid < 64) {
                const float4* p = reinterpret_cast<const float4*>(g_tpart + b * TCH * 256);
                float4 r = p[tid];               // fixed order j=0..7
                #pragma unroll
                for (int j = 1; j < TCH; j++) f4_add(r, p[j * 64 + tid]);
                r.x *= scale; r.y *= scale; r.z *= scale; r.w *= scale;
                reinterpret_cast<float4*>(out + b * 512 + 256)[tid] = r;
            }
            if (tid == 0) g_ttk[b] = 0;   // reset for next graph replay
        }
    }
}

extern "C" void kernel_launch(void* const* d_in, const int* in_sizes, int n_in,
                              void* d_out, int out_size) {
    const float* drug_x    = (const float*)d_in[0];
    const int*   batch_idx = (const int*)d_in[1];
    const float* target_h  = (const float*)d_in[2];
    // d_in[3] (W_a) cancels out mathematically; unused.
    float* out = (float*)d_out;
    int n_nodes = in_sizes[1];

    dim3 grid(BATCH_B, 4 + TCH);   // 64 x 12 = 768 blocks
    drugban_fused_kernel<<<grid, 256>>>(drug_x, batch_idx, target_h, out, n_nodes);
}